// round 4
// baseline (speedup 1.0000x reference)
#include <cuda_runtime.h>
#include <mma.h>
#include <cstdint>

using namespace nvcuda;

// Problem dims
#define BT   512          // T
#define BB   128          // B
#define II   512          // I
#define HH   1024         // H
#define TGTD 128          // TGT
#define MROWS (BT*BB)     // 65536

// big-GEMM tile config (proj / head)
#define BM 128
#define BN 64
#define BK 16
#define BKP 24
#define BNP 72
#define NTHREADS 256

// persistent recurrence config
#define NBLK 128

// ---------------- scratch (static device memory; no allocation) ----------------
__device__ float g_h  [2][BB][HH];
__device__ float g_rh [2][BB][HH];
__device__ float g_u  [2][BB][HH];
__device__ float g_xp [2][3][MROWS][HH];
__device__ float g_hcat[MROWS][2*HH];

__device__ unsigned g_bar_count = 0;
__device__ unsigned g_bar_epoch = 0;

__device__ __forceinline__ float sigmoidf_(float x) { return 1.0f / (1.0f + expf(-x)); }

// ---------------- grid-wide epoch barrier (persistent kernel) ----------------
__device__ __forceinline__ void grid_barrier()
{
    __syncthreads();
    if (threadIdx.x == 0) {
        volatile unsigned* ep = &g_bar_epoch;
        unsigned e = *ep;
        __threadfence();
        if (atomicAdd(&g_bar_count, 1u) == NBLK - 1) {
            g_bar_count = 0;
            __threadfence();
            *ep = e + 1;
        } else {
            while (*ep == e) { __nanosleep(64); }
        }
        __threadfence();
    }
    __syncthreads();
}

// ---------------- big tf32 GEMM core (proj / head kernels) ----------------
template<typename RowPtrF, typename EpiF>
__device__ __forceinline__ void gemm_tile(int K, RowPtrF rowA, const float* Bp, int ldb, EpiF epi)
{
    __shared__ __align__(16) union SmU {
        struct { float A[2][BM][BKP]; float B[2][BK][BNP]; } t;
        float ep[BM][BNP];
    } sm;

    const int tid = threadIdx.x;
    const int wid = tid >> 5;
    const int wm0 = (wid & 3) * 32;
    const int wn0 = (wid >> 2) * 32;

    wmma::fragment<wmma::accumulator, 16, 16, 8, float> acc[2][2];
#pragma unroll
    for (int i = 0; i < 2; i++)
#pragma unroll
        for (int j = 0; j < 2; j++) wmma::fill_fragment(acc[i][j], 0.0f);

    const int a_row = tid >> 2;
    const int a_col = (tid & 3) << 2;
    const float* arp0 = rowA(a_row)      + a_col;
    const float* arp1 = rowA(a_row + 64) + a_col;
    const int b_row = tid >> 4;
    const int b_col = (tid & 15) << 2;
    const float* brp = Bp + (size_t)b_row * ldb + b_col;

    float4 av0 = *(const float4*)(arp0);
    float4 av1 = *(const float4*)(arp1);
    float4 bv  = *(const float4*)(brp);

    const int nIter = K / BK;
    for (int it = 0; it < nIter; ++it) {
        const int p = it & 1;
        *(float4*)&sm.t.A[p][a_row     ][a_col] = av0;
        *(float4*)&sm.t.A[p][a_row + 64][a_col] = av1;
        *(float4*)&sm.t.B[p][b_row][b_col]      = bv;
        __syncthreads();
        if (it + 1 < nIter) {
            const int k0 = (it + 1) * BK;
            av0 = *(const float4*)(arp0 + k0);
            av1 = *(const float4*)(arp1 + k0);
            bv  = *(const float4*)(brp + (size_t)k0 * ldb);
        }
#pragma unroll
        for (int ks = 0; ks < BK; ks += 8) {
            wmma::fragment<wmma::matrix_a, 16, 16, 8, wmma::precision::tf32, wmma::row_major> af[2];
            wmma::fragment<wmma::matrix_b, 16, 16, 8, wmma::precision::tf32, wmma::row_major> bf[2];
#pragma unroll
            for (int i = 0; i < 2; i++) {
                wmma::load_matrix_sync(af[i], &sm.t.A[p][wm0 + i * 16][ks], BKP);
#pragma unroll
                for (int e = 0; e < af[i].num_elements; e++)
                    af[i].x[e] = wmma::__float_to_tf32(af[i].x[e]);
            }
#pragma unroll
            for (int j = 0; j < 2; j++) {
                wmma::load_matrix_sync(bf[j], &sm.t.B[p][ks][wn0 + j * 16], BNP);
#pragma unroll
                for (int e = 0; e < bf[j].num_elements; e++)
                    bf[j].x[e] = wmma::__float_to_tf32(bf[j].x[e]);
            }
#pragma unroll
            for (int i = 0; i < 2; i++)
#pragma unroll
                for (int j = 0; j < 2; j++)
                    wmma::mma_sync(acc[i][j], af[i], bf[j], acc[i][j]);
        }
    }

    __syncthreads();
#pragma unroll
    for (int i = 0; i < 2; i++)
#pragma unroll
        for (int j = 0; j < 2; j++)
            wmma::store_matrix_sync(&sm.ep[wm0 + i * 16][wn0 + j * 16], acc[i][j], BNP,
                                    wmma::mem_row_major);
    __syncthreads();
#pragma unroll
    for (int e = 0; e < (BM * BN) / NTHREADS; e++) {
        const int idx = tid + e * NTHREADS;
        const int m = idx >> 6;
        const int n = idx & 63;
        epi(m, n, sm.ep[m][n]);
    }
}

// ---------------- small tf32 GEMM core (64 x TBN, K arbitrary) ----------------
// 256 threads, 8 warps as 4(m) x 2(n); warp tile 16 x (TBN/2).
#define SMRAW_BYTES 21504
template<int TBN, typename RowPtrF, typename EpiF>
__device__ __forceinline__ void gemm64(char* smraw, int K, RowPtrF rowA, const float* Bp,
                                       int ldb, EpiF epi)
{
    constexpr int TBNP = TBN + 8;
    constexpr int NF   = TBN / 32;          // n-fragments per warp
    float (*sA)[64][BKP]  = reinterpret_cast<float (*)[64][BKP]>(smraw);
    float (*sB)[16][TBNP] = reinterpret_cast<float (*)[16][TBNP]>(smraw + 2 * 64 * BKP * 4);
    float (*sE)[TBNP]     = reinterpret_cast<float (*)[TBNP]>(smraw);

    const int tid = threadIdx.x;
    const int wid = tid >> 5;
    const int wm0 = (wid & 3) * 16;
    const int wn0 = (wid >> 2) * (TBN / 2);

    wmma::fragment<wmma::accumulator, 16, 16, 8, float> acc[NF];
#pragma unroll
    for (int j = 0; j < NF; j++) wmma::fill_fragment(acc[j], 0.0f);

    const int a_row = tid >> 2;             // 0..63
    const int a_col = (tid & 3) << 2;
    const float* arp = rowA(a_row) + a_col;

    constexpr int BQ = TBN / 4;             // float4 per B row
    constexpr int NLOADB = 16 * BQ;         // threads that load B
    const int b_row = tid / BQ;
    const int b_col = (tid % BQ) << 2;
    const bool bpred = tid < NLOADB;
    const float* brp = Bp + (size_t)b_row * ldb + b_col;

    float4 av = *(const float4*)(arp);
    float4 bv = bpred ? *(const float4*)(brp) : make_float4(0.f, 0.f, 0.f, 0.f);

    const int nIter = K / BK;
    for (int it = 0; it < nIter; ++it) {
        const int p = it & 1;
        *(float4*)&sA[p][a_row][a_col] = av;
        if (bpred) *(float4*)&sB[p][b_row][b_col] = bv;
        __syncthreads();
        if (it + 1 < nIter) {
            const int k0 = (it + 1) * BK;
            av = *(const float4*)(arp + k0);
            if (bpred) bv = *(const float4*)(brp + (size_t)k0 * ldb);
        }
#pragma unroll
        for (int ks = 0; ks < BK; ks += 8) {
            wmma::fragment<wmma::matrix_a, 16, 16, 8, wmma::precision::tf32, wmma::row_major> af;
            wmma::fragment<wmma::matrix_b, 16, 16, 8, wmma::precision::tf32, wmma::row_major> bf[NF];
            wmma::load_matrix_sync(af, &sA[p][wm0][ks], BKP);
#pragma unroll
            for (int e = 0; e < af.num_elements; e++)
                af.x[e] = wmma::__float_to_tf32(af.x[e]);
#pragma unroll
            for (int j = 0; j < NF; j++) {
                wmma::load_matrix_sync(bf[j], &sB[p][ks][wn0 + j * 16], TBNP);
#pragma unroll
                for (int e = 0; e < bf[j].num_elements; e++)
                    bf[j].x[e] = wmma::__float_to_tf32(bf[j].x[e]);
#pragma unroll
                for (int q = 0; q < 1; q++)
                    wmma::mma_sync(acc[j], af, bf[j], acc[j]);
            }
        }
        __syncthreads();
    }

#pragma unroll
    for (int j = 0; j < NF; j++)
        wmma::store_matrix_sync(&sE[wm0][wn0 + j * 16], acc[j], TBNP, wmma::mem_row_major);
    __syncthreads();
#pragma unroll
    for (int e = 0; e < (64 * TBN) / 256; e++) {
        const int idx = tid + e * 256;
        const int m = idx / TBN;
        const int n = idx % TBN;
        epi(m, n, sE[m][n]);
    }
    __syncthreads();   // smem reused next stage
}

// ---------------- kernels ----------------

__global__ void zero_h_kernel()
{
    int i = blockIdx.x * blockDim.x + threadIdx.x;
    ((float*)g_h)[i] = 0.0f;
}

struct ProjArgs {
    const float* X[2];
    const float* W[2][3];
    const float* bias[2][3];
};

__global__ void __launch_bounds__(NTHREADS) proj_kernel(ProjArgs a)
{
    const int d  = blockIdx.z;
    const int m0 = blockIdx.y * BM;
    const int n0 = blockIdx.x * BN;
    const int g  = n0 >> 10;
    const int nb = n0 & 1023;
    const float* X  = a.X[d];
    const float* Bp = a.W[d][g] + nb;
    const float* bs = a.bias[d][g];
    float* out = &g_xp[d][g][0][0];

    auto rowA = [&](int m) -> const float* {
        const int r = m0 + m;
        const int t = r >> 7;
        const int b = r & 127;
        return X + ((size_t)b * BT + t) * II;
    };
    auto epi = [&](int m, int n, float v) {
        const int r = m0 + m;
        const int c = nb + n;
        out[(size_t)r * HH + c] = v + bs[c];
    };
    gemm_tile(II, rowA, Bp, HH, epi);
}

struct RecArgs {
    const float* U[2][2];     // [dir][0=Ur,1=Uu]
    const float* Uh[2];
};

// Persistent recurrence: NBLK=128 CTAs, whole T loop inside, grid barrier between stages.
__global__ void __launch_bounds__(256) recur_kernel(RecArgs a)
{
    __shared__ __align__(16) char smraw[SMRAW_BYTES];
    const int tile = blockIdx.x;

    // stage1 decode: 2 dirs x 2 gates x 2 mhalves x 16 coltiles
    const int s1_ct = tile & 15;
    const int s1_mh = (tile >> 4) & 1;
    const int s1_g  = (tile >> 5) & 1;
    const int s1_d  = tile >> 6;
    // stage2 decode: 2 dirs x 2 mhalves x 32 coltiles
    const int s2_ct = tile & 31;
    const int s2_mh = (tile >> 5) & 1;
    const int s2_d  = tile >> 6;

    for (int t = 0; t < BT; ++t) {
        {   // ---- stage 1: r and u gates ----
            const float* hrow = &g_h[s1_d][s1_mh * 64][0];
            const float* Bp   = a.U[s1_d][s1_g] + s1_ct * 64;
            const float* xg   = &g_xp[s1_d][s1_g][(size_t)t * BB + s1_mh * 64][0];
            float* outb = s1_g ? &g_u[s1_d][s1_mh * 64][0] : &g_rh[s1_d][s1_mh * 64][0];

            auto rowA = [&](int m) -> const float* { return hrow + (size_t)m * HH; };
            auto epi = [&](int m, int n, float v) {
                const int c = s1_ct * 64 + n;
                const float s = sigmoidf_(xg[(size_t)m * HH + c] + v);
                outb[(size_t)m * HH + c] = s1_g ? s : s * hrow[(size_t)m * HH + c];
            };
            gemm64<64>(smraw, HH, rowA, Bp, HH, epi);
        }
        grid_barrier();
        {   // ---- stage 2: candidate + state update ----
            const float* rhrow = &g_rh[s2_d][s2_mh * 64][0];
            const float* Bp    = a.Uh[s2_d] + s2_ct * 32;
            const float* xh    = &g_xp[s2_d][2][(size_t)t * BB + s2_mh * 64][0];

            auto rowA = [&](int m) -> const float* { return rhrow + (size_t)m * HH; };
            auto epi = [&](int m, int n, float v) {
                const int c   = s2_ct * 32 + n;
                const int row = s2_mh * 64 + m;
                const float cand = tanhf(xh[(size_t)m * HH + c] + v);
                const float u  = g_u[s2_d][row][c];
                const float hp = g_h[s2_d][row][c];
                const float hn = u * hp + (1.0f - u) * cand;
                g_h[s2_d][row][c] = hn;
                g_hcat[(size_t)t * BB + row][s2_d * HH + c] = hn;
            };
            gemm64<32>(smraw, HH, rowA, Bp, HH, epi);
        }
        grid_barrier();
    }
}

__global__ void __launch_bounds__(NTHREADS) out_kernel(const float* __restrict__ Wo,
                                                       const float* __restrict__ bo,
                                                       float* __restrict__ out)
{
    const int m0 = blockIdx.y * BM;
    const int n0 = blockIdx.x * BN;
    const float* Bp = Wo + n0;

    auto rowA = [&](int m) -> const float* { return &g_hcat[m0 + m][0]; };
    auto epi = [&](int m, int n, float v) {
        const int c = n0 + n;
        out[(size_t)(m0 + m) * TGTD + c] = sigmoidf_(v + bo[c]);
    };
    gemm_tile(2 * HH, rowA, Bp, TGTD, epi);
}

// ---------------- launch ----------------
extern "C" void kernel_launch(void* const* d_in, const int* in_sizes, int n_in,
                              void* d_out, int out_size)
{
    (void)in_sizes; (void)n_in; (void)out_size;
    const float* fwd = (const float*)d_in[0];
    const float* bwd = (const float*)d_in[1];
    const float* Wr  = (const float*)d_in[2];
    const float* Ur  = (const float*)d_in[3];
    const float* br  = (const float*)d_in[4];
    const float* Wu  = (const float*)d_in[5];
    const float* Uu  = (const float*)d_in[6];
    const float* bu  = (const float*)d_in[7];
    const float* Wh  = (const float*)d_in[8];
    const float* Uh  = (const float*)d_in[9];
    const float* bh  = (const float*)d_in[10];
    const float* Wr1 = (const float*)d_in[11];
    const float* Ur1 = (const float*)d_in[12];
    const float* br1 = (const float*)d_in[13];
    const float* Wu1 = (const float*)d_in[14];
    const float* Uu1 = (const float*)d_in[15];
    const float* bu1 = (const float*)d_in[16];
    const float* Wh1 = (const float*)d_in[17];
    const float* Uh1 = (const float*)d_in[18];
    const float* bh1 = (const float*)d_in[19];
    const float* Wo  = (const float*)d_in[20];
    const float* bo  = (const float*)d_in[21];
    float* out = (float*)d_out;

    zero_h_kernel<<<(2 * BB * HH) / 1024, 1024>>>();

    ProjArgs pa;
    pa.X[0] = fwd;  pa.X[1] = bwd;
    pa.W[0][0] = Wr;  pa.W[0][1] = Wu;  pa.W[0][2] = Wh;
    pa.W[1][0] = Wr1; pa.W[1][1] = Wu1; pa.W[1][2] = Wh1;
    pa.bias[0][0] = br;  pa.bias[0][1] = bu;  pa.bias[0][2] = bh;
    pa.bias[1][0] = br1; pa.bias[1][1] = bu1; pa.bias[1][2] = bh1;
    proj_kernel<<<dim3(3 * HH / BN, MROWS / BM, 2), NTHREADS>>>(pa);

    RecArgs ra;
    ra.U[0][0] = Ur;  ra.U[0][1] = Uu;
    ra.U[1][0] = Ur1; ra.U[1][1] = Uu1;
    ra.Uh[0] = Uh; ra.Uh[1] = Uh1;
    recur_kernel<<<NBLK, 256>>>(ra);

    out_kernel<<<dim3(TGTD / BN, MROWS / BM, 1), NTHREADS>>>(Wo, bo, out);
}

// round 6
// speedup vs baseline: 2.6668x; 2.6668x over previous
#include <cuda_runtime.h>
#include <cuda_fp16.h>
#include <mma.h>
#include <cstdint>

using namespace nvcuda;

// Problem dims
#define BT   512
#define BB   128
#define II   512
#define HH   1024
#define TGTD 128
#define MROWS (BT*BB)

#define NTHREADS 256
#define NBLK 128            // persistent recurrence CTAs (64 per direction)

// ---------------- scratch (static device memory; no allocation) ----------------
__device__ float  g_h  [2][BB][HH];            // master hidden state (fp32)
__device__ __half g_hh [2][BB][HH];            // fp16 mirror of h (GEMM A operand)
__device__ __half g_rhh[2][BB][HH];            // r*h (fp16, GEMM A operand)
__device__ float  g_u  [2][BB][HH];            // update gate (fp32)
__device__ __half g_xh [2][BB*BT*II];          // fp16 inputs
__device__ __half g_wh [2][3][II*HH];          // fp16 input weights
__device__ __half g_woh[2*HH*TGTD];            // fp16 output weights
__device__ __half g_xp [2][3][MROWS][HH];      // input projections (+bias), fp16
__device__ __half g_hcat[MROWS][2*HH];         // concatenated hiddens, fp16

__device__ unsigned g_bar_count = 0;
__device__ unsigned g_bar_epoch = 0;

__device__ __forceinline__ float sigmoidf_(float x) { return 1.0f / (1.0f + expf(-x)); }

// ---------------- grid-wide epoch barrier ----------------
__device__ __forceinline__ void grid_barrier()
{
    __threadfence();
    __syncthreads();
    if (threadIdx.x == 0) {
        volatile unsigned* ep = &g_bar_epoch;
        unsigned e = *ep;
        if (atomicAdd(&g_bar_count, 1u) == NBLK - 1) {
            g_bar_count = 0;
            __threadfence();
            *ep = e + 1;
        } else {
            while (*ep == e) { __nanosleep(64); }
        }
        __threadfence();
    }
    __syncthreads();
}

// ---------------- fp16 GEMM core for proj / head (128 x 64 tile) ----------------
template<typename RowPtrF, typename EpiF>
__device__ __forceinline__ void gemm_tile_h(int K, RowPtrF rowA, const __half* Bp, int ldb,
                                            EpiF epi)
{
    __shared__ __align__(16) union SmU {
        struct { __half A[2][128][40]; __half B[2][32][72]; } t;
        float ep[128][72];
    } sm;

    const int tid = threadIdx.x;
    const int wid = tid >> 5;
    const int wm0 = (wid & 3) * 32;
    const int wn0 = (wid >> 2) * 32;

    wmma::fragment<wmma::accumulator, 16, 16, 16, float> acc[2][2];
#pragma unroll
    for (int i = 0; i < 2; i++)
#pragma unroll
        for (int j = 0; j < 2; j++) wmma::fill_fragment(acc[i][j], 0.0f);

    const int r0 = tid >> 2;
    const int aq = (tid & 3) * 8;
    const __half* arp0 = rowA(r0)      + aq;
    const __half* arp1 = rowA(r0 + 64) + aq;
    const int b_row = tid >> 3;
    const int bq = (tid & 7) * 8;
    const __half* brp = Bp + (size_t)b_row * ldb + bq;

    uint4 av0 = *(const uint4*)arp0;
    uint4 av1 = *(const uint4*)arp1;
    uint4 bv  = *(const uint4*)brp;

    const int nIter = K / 32;
    for (int it = 0; it < nIter; ++it) {
        const int p = it & 1;
        *(uint4*)&sm.t.A[p][r0][aq]       = av0;
        *(uint4*)&sm.t.A[p][r0 + 64][aq]  = av1;
        *(uint4*)&sm.t.B[p][b_row][bq]    = bv;
        __syncthreads();
        if (it + 1 < nIter) {
            const int k0 = (it + 1) * 32;
            av0 = *(const uint4*)(arp0 + k0);
            av1 = *(const uint4*)(arp1 + k0);
            bv  = *(const uint4*)(brp + (size_t)k0 * ldb);
        }
#pragma unroll
        for (int ks = 0; ks < 32; ks += 16) {
            wmma::fragment<wmma::matrix_a, 16, 16, 16, __half, wmma::row_major> af[2];
            wmma::fragment<wmma::matrix_b, 16, 16, 16, __half, wmma::row_major> bf[2];
#pragma unroll
            for (int i = 0; i < 2; i++)
                wmma::load_matrix_sync(af[i], &sm.t.A[p][wm0 + i * 16][ks], 40);
#pragma unroll
            for (int j = 0; j < 2; j++)
                wmma::load_matrix_sync(bf[j], &sm.t.B[p][ks][wn0 + j * 16], 72);
#pragma unroll
            for (int i = 0; i < 2; i++)
#pragma unroll
                for (int j = 0; j < 2; j++)
                    wmma::mma_sync(acc[i][j], af[i], bf[j], acc[i][j]);
        }
    }

    __syncthreads();
#pragma unroll
    for (int i = 0; i < 2; i++)
#pragma unroll
        for (int j = 0; j < 2; j++)
            wmma::store_matrix_sync(&sm.ep[wm0 + i * 16][wn0 + j * 16], acc[i][j], 72,
                                    wmma::mem_row_major);
    __syncthreads();
#pragma unroll
    for (int e = 0; e < 32; e++) {
        const int idx = tid + e * 256;
        const int m = idx >> 6;
        const int n = idx & 63;
        epi(m, n, sm.ep[m][n]);
    }
}

// ---------------- recurrence phase GEMM: [128 x 1024] x [1024 x NC], B in smem ----------------
// MFRAG=2 -> NC=32 (warps 4m x 2n, 32x16 tiles); MFRAG=1 -> NC=16 (8m x 1n, 16x16).
template<int NC, int MFRAG, typename EpiF>
__device__ __forceinline__ void rec_phase(const __half* __restrict__ Aglob,
                                          const __half* __restrict__ sW,
                                          __half* __restrict__ sA,
                                          float* __restrict__ sE,
                                          EpiF epi)
{
    const int tid = threadIdx.x;
    const int wid = tid >> 5;
    const int wm0 = (MFRAG == 2) ? (wid & 3) * 32 : wid * 16;
    const int wn0 = (MFRAG == 2) ? (wid >> 2) * 16 : 0;

    wmma::fragment<wmma::accumulator, 16, 16, 16, float> acc[MFRAG];
#pragma unroll
    for (int i = 0; i < MFRAG; i++) wmma::fill_fragment(acc[i], 0.0f);

    const int r  = tid >> 3;          // 0..31
    const int c8 = (tid & 7) * 8;     // 0..56

    uint4 v[4];
#pragma unroll
    for (int i = 0; i < 4; i++)
        v[i] = *(const uint4*)(Aglob + (size_t)(r + 32 * i) * HH + c8);

    for (int it = 0; it < 16; ++it) {
        __half* dst = sA + (it & 1) * (128 * 72);
#pragma unroll
        for (int i = 0; i < 4; i++)
            *(uint4*)(dst + (r + 32 * i) * 72 + c8) = v[i];
        __syncthreads();
        if (it < 15) {
            const int k0 = (it + 1) * 64;
#pragma unroll
            for (int i = 0; i < 4; i++)
                v[i] = *(const uint4*)(Aglob + (size_t)(r + 32 * i) * HH + k0 + c8);
        }
        const __half* Ab = sA + (it & 1) * (128 * 72);
#pragma unroll
        for (int ks = 0; ks < 64; ks += 16) {
            wmma::fragment<wmma::matrix_a, 16, 16, 16, __half, wmma::row_major> af[MFRAG];
            wmma::fragment<wmma::matrix_b, 16, 16, 16, __half, wmma::row_major> bf;
#pragma unroll
            for (int i = 0; i < MFRAG; i++)
                wmma::load_matrix_sync(af[i], Ab + (wm0 + 16 * i) * 72 + ks, 72);
            wmma::load_matrix_sync(bf, sW + (it * 64 + ks) * NC + wn0, NC);
#pragma unroll
            for (int i = 0; i < MFRAG; i++)
                wmma::mma_sync(acc[i], af[i], bf, acc[i]);
        }
    }
    __syncthreads();
#pragma unroll
    for (int i = 0; i < MFRAG; i++)
        wmma::store_matrix_sync(sE + (wm0 + 16 * i) * (NC + 4) + wn0, acc[i], NC + 4,
                                wmma::mem_row_major);
    __syncthreads();
    for (int e = tid; e < 128 * NC; e += 256) {
        const int m = e / NC;
        const int n = e % NC;
        epi(m, n, sE[m * (NC + 4) + n]);
    }
    __syncthreads();
}

// ---------------- kernels ----------------

__global__ void zero_h_kernel()
{
    int i = blockIdx.x * blockDim.x + threadIdx.x;
    ((float*)g_h)[i] = 0.0f;
    ((__half*)g_hh)[i] = __float2half(0.0f);
}

struct alignas(8) H4 { __half2 a, b; };

__device__ __forceinline__ H4 f2h4(float4 vv)
{
    H4 o;
    o.a = __floats2half2_rn(vv.x, vv.y);
    o.b = __floats2half2_rn(vv.z, vv.w);
    return o;
}

// converts inputs into g_xh[dir]
__global__ void f2h_x_kernel(const float4* __restrict__ src, int dir)
{
    int i = blockIdx.x * blockDim.x + threadIdx.x;
    ((H4*)&g_xh[dir][0])[i] = f2h4(src[i]);
}

// converts one W matrix into g_wh[slot/3][slot%3]
__global__ void f2h_w_kernel(const float4* __restrict__ src, int slot)
{
    int i = blockIdx.x * blockDim.x + threadIdx.x;
    ((H4*)&g_wh[slot / 3][slot % 3][0])[i] = f2h4(src[i]);
}

__global__ void f2h_wo_kernel(const float4* __restrict__ src)
{
    int i = blockIdx.x * blockDim.x + threadIdx.x;
    ((H4*)&g_woh[0])[i] = f2h4(src[i]);
}

struct ProjArgs { const float* bias[2][3]; };

// grid (48, 512, 2)
__global__ void __launch_bounds__(NTHREADS) proj_kernel(ProjArgs a)
{
    const int d  = blockIdx.z;
    const int m0 = blockIdx.y * 128;
    const int n0 = blockIdx.x * 64;
    const int g  = n0 >> 10;
    const int nb = n0 & 1023;
    const __half* X  = g_xh[d];
    const __half* Bp = g_wh[d][g] + nb;
    const float*  bs = a.bias[d][g];

    auto rowA = [&](int m) -> const __half* {
        const int rr = m0 + m;
        const int t = rr >> 7;
        const int b = rr & 127;
        return X + ((size_t)b * BT + t) * II;
    };
    auto epi = [&](int m, int n, float vv) {
        const int rr = m0 + m;
        const int c = nb + n;
        g_xp[d][g][rr][c] = __float2half(vv + bs[c]);
    };
    gemm_tile_h(II, rowA, Bp, HH, epi);
}

struct RecArgs { const float* U[2][2]; const float* Uh[2]; };

// Persistent recurrence: 128 CTAs; weights resident in smem for all T steps.
__global__ void __launch_bounds__(256) recur_kernel(RecArgs a)
{
    extern __shared__ __align__(16) char rsm[];
    __half* sW1 = (__half*)rsm;                        // 1024 x 32  (65536 B)
    __half* sW2 = (__half*)(rsm + 65536);              // 1024 x 16  (32768 B)
    __half* sA  = (__half*)(rsm + 98304);              // 2 x 128 x 72 (36864 B)
    float*  sE  = (float*)(rsm + 98304);               // aliased staging

    const int tid = threadIdx.x;
    const int s = blockIdx.x & 63;                     // column slice
    const int d = blockIdx.x >> 6;                     // direction
    const int g1 = s >> 5;                             // phase1 gate (0=r,1=u)
    const int col0 = (s & 31) * 32;                    // phase1 col base within gate
    const int col2 = s * 16;                           // phase2 col base

    // Load weight slices into smem (fp32 -> fp16), once.
    {
        const float* src1 = a.U[d][g1];
#pragma unroll
        for (int i = 0; i < 32; i++) {
            const int idx = tid + i * 256;
            const int k = idx >> 3, q = idx & 7;
            float4 w = *(const float4*)(src1 + (size_t)k * HH + col0 + q * 4);
            *(__half2*)(sW1 + k * 32 + q * 4)     = __floats2half2_rn(w.x, w.y);
            *(__half2*)(sW1 + k * 32 + q * 4 + 2) = __floats2half2_rn(w.z, w.w);
        }
        const float* src2 = a.Uh[d];
#pragma unroll
        for (int i = 0; i < 16; i++) {
            const int idx = tid + i * 256;
            const int k = idx >> 2, q = idx & 3;
            float4 w = *(const float4*)(src2 + (size_t)k * HH + col2 + q * 4);
            *(__half2*)(sW2 + k * 16 + q * 4)     = __floats2half2_rn(w.x, w.y);
            *(__half2*)(sW2 + k * 16 + q * 4 + 2) = __floats2half2_rn(w.z, w.w);
        }
    }
    __syncthreads();

    for (int t = 0; t < BT; ++t) {
        {   // phase 1: r / u gate for this CTA's 32 columns
            const __half* xg = &g_xp[d][g1][(size_t)t * BB][0];
            auto epi = [&](int m, int n, float vv) {
                const int c = col0 + n;
                const float sg = sigmoidf_(__half2float(xg[(size_t)m * HH + c]) + vv);
                if (g1 == 0) g_rhh[d][m][c] = __float2half(sg * g_h[d][m][c]);
                else         g_u[d][m][c] = sg;
            };
            rec_phase<32, 2>(&g_hh[d][0][0], sW1, sA, sE, epi);
        }
        grid_barrier();
        {   // phase 2: candidate + state update for 16 columns
            const __half* xh = &g_xp[d][2][(size_t)t * BB][0];
            auto epi = [&](int m, int n, float vv) {
                const int c = col2 + n;
                const float cand = tanhf(__half2float(xh[(size_t)m * HH + c]) + vv);
                const float uu = g_u[d][m][c];
                const float hp = g_h[d][m][c];
                const float hn = uu * hp + (1.0f - uu) * cand;
                g_h[d][m][c] = hn;
                const __half hh = __float2half(hn);
                g_hh[d][m][c] = hh;
                g_hcat[(size_t)t * BB + m][d * HH + c] = hh;
            };
            rec_phase<16, 1>(&g_rhh[d][0][0], sW2, sA, sE, epi);
        }
        grid_barrier();
    }
}

// grid (2, 512)
__global__ void __launch_bounds__(NTHREADS) out_kernel(const float* __restrict__ bo,
                                                       float* __restrict__ out)
{
    const int m0 = blockIdx.y * 128;
    const int n0 = blockIdx.x * 64;
    const __half* Bp = g_woh + n0;

    auto rowA = [&](int m) -> const __half* { return &g_hcat[m0 + m][0]; };
    auto epi = [&](int m, int n, float vv) {
        const int c = n0 + n;
        out[(size_t)(m0 + m) * TGTD + c] = sigmoidf_(vv + bo[c]);
    };
    gemm_tile_h(2 * HH, rowA, Bp, TGTD, epi);
}

// ---------------- launch ----------------
extern "C" void kernel_launch(void* const* d_in, const int* in_sizes, int n_in,
                              void* d_out, int out_size)
{
    (void)in_sizes; (void)n_in; (void)out_size;
    const float* fwd = (const float*)d_in[0];
    const float* bwd = (const float*)d_in[1];
    const float* Wr  = (const float*)d_in[2];
    const float* Ur  = (const float*)d_in[3];
    const float* br  = (const float*)d_in[4];
    const float* Wu  = (const float*)d_in[5];
    const float* Uu  = (const float*)d_in[6];
    const float* bu  = (const float*)d_in[7];
    const float* Wh  = (const float*)d_in[8];
    const float* Uh  = (const float*)d_in[9];
    const float* bh  = (const float*)d_in[10];
    const float* Wr1 = (const float*)d_in[11];
    const float* Ur1 = (const float*)d_in[12];
    const float* br1 = (const float*)d_in[13];
    const float* Wu1 = (const float*)d_in[14];
    const float* Uu1 = (const float*)d_in[15];
    const float* bu1 = (const float*)d_in[16];
    const float* Wh1 = (const float*)d_in[17];
    const float* Uh1 = (const float*)d_in[18];
    const float* bh1 = (const float*)d_in[19];
    const float* Wo  = (const float*)d_in[20];
    const float* bo  = (const float*)d_in[21];
    float* out = (float*)d_out;

    zero_h_kernel<<<(2 * BB * HH) / 1024, 1024>>>();

    // fp32 -> fp16 conversions (device symbols addressed in-kernel)
    {
        const int nx4 = (BB * BT * II) / 4;                       // 8388608
        f2h_x_kernel<<<nx4 / 256, 256>>>((const float4*)fwd, 0);
        f2h_x_kernel<<<nx4 / 256, 256>>>((const float4*)bwd, 1);
        const int nw4 = (II * HH) / 4;                            // 131072
        const float* Ws[6] = {Wr, Wu, Wh, Wr1, Wu1, Wh1};
        for (int i = 0; i < 6; i++)
            f2h_w_kernel<<<nw4 / 256, 256>>>((const float4*)Ws[i], i);
        const int no4 = (2 * HH * TGTD) / 4;                      // 65536
        f2h_wo_kernel<<<no4 / 256, 256>>>((const float4*)Wo);
    }

    ProjArgs pa;
    pa.bias[0][0] = br;  pa.bias[0][1] = bu;  pa.bias[0][2] = bh;
    pa.bias[1][0] = br1; pa.bias[1][1] = bu1; pa.bias[1][2] = bh1;
    proj_kernel<<<dim3(3 * HH / 64, MROWS / 128, 2), NTHREADS>>>(pa);

    RecArgs ra;
    ra.U[0][0] = Ur;  ra.U[0][1] = Uu;
    ra.U[1][0] = Ur1; ra.U[1][1] = Uu1;
    ra.Uh[0] = Uh; ra.Uh[1] = Uh1;
    const int rec_smem = 65536 + 32768 + 36864;   // 135168
    cudaFuncSetAttribute(recur_kernel, cudaFuncAttributeMaxDynamicSharedMemorySize, rec_smem);
    recur_kernel<<<NBLK, 256, rec_smem>>>(ra);

    out_kernel<<<dim3(TGTD / 64, MROWS / 128, 1), NTHREADS>>>(bo, out);
}

// round 9
// speedup vs baseline: 4.1096x; 1.5410x over previous
#include <cuda_runtime.h>
#include <cuda_fp16.h>
#include <mma.h>
#include <cstdint>

using namespace nvcuda;

// Problem dims
#define BT   512
#define BB   128
#define II   512
#define HH   1024
#define TGTD 128
#define MROWS (BT*BB)

#define NBLK 128            // persistent recurrence CTAs (64 per direction)

// ---------------- scratch (static device memory; no allocation) ----------------
__device__ float  g_h  [2][BB][HH];            // master hidden state (fp32)
__device__ __half g_hh [2][BB][HH];            // fp16 mirror of h
__device__ __half g_rhh[2][BB][HH];            // r*h (fp16)
__device__ float  g_u  [2][BB][HH];            // update gate (fp32)
__device__ __half g_xh [2][BB*BT*II];          // fp16 inputs
__device__ __half g_wh [2][3][II*HH];          // fp16 input weights
__device__ __half g_woh[2*HH*TGTD];            // fp16 output weights
__device__ __half g_xp [2][3][MROWS][HH];      // input projections (+bias), fp16
__device__ __half g_hcat[MROWS][2*HH];         // concatenated hiddens, fp16

__device__ unsigned g_bar_count = 0;
__device__ unsigned g_bar_epoch = 0;

__device__ __forceinline__ float sigmoidf_(float x) { return 1.0f / (1.0f + __expf(-x)); }

// ---------------- cp.async helpers ----------------
__device__ __forceinline__ void cpa16(uint32_t dst_smem, const void* src)
{
    asm volatile("cp.async.cg.shared.global [%0], [%1], 16;\n" :: "r"(dst_smem), "l"(src));
}
__device__ __forceinline__ void cpa_commit()
{
    asm volatile("cp.async.commit_group;\n" ::);
}
template<int N>
__device__ __forceinline__ void cpa_wait()
{
    asm volatile("cp.async.wait_group %0;\n" :: "n"(N));
}

// ---------------- grid-wide epoch barrier ----------------
__device__ __forceinline__ void grid_barrier()
{
    __threadfence();
    __syncthreads();
    if (threadIdx.x == 0) {
        volatile unsigned* ep = &g_bar_epoch;
        unsigned e = *ep;
        if (atomicAdd(&g_bar_count, 1u) == NBLK - 1) {
            g_bar_count = 0;
            __threadfence();
            *ep = e + 1;
        } else {
            while (*ep == e) { __nanosleep(32); }
        }
        __threadfence();
    }
    __syncthreads();
}

// ---------------- fp16 GEMM core for proj / head (128 x 128 tile, BK=32) ----------------
// Dynamic smem: max(2*128*40*2 + 2*32*136*2, 128*136*4) = 69632 bytes.
#define GEMM128_SMEM 69632
template<typename RowPtrF, typename EpiF>
__device__ __forceinline__ void gemm128(int K, RowPtrF rowA, const __half* Bp, int ldb,
                                        EpiF epi)
{
    extern __shared__ __align__(16) char dsm[];
    __half (*sA)[128][40]  = reinterpret_cast<__half (*)[128][40]>(dsm);
    __half (*sB)[32][136]  = reinterpret_cast<__half (*)[32][136]>(dsm + 2 * 128 * 40 * 2);
    float  (*sE)[136]      = reinterpret_cast<float (*)[136]>(dsm);

    const int tid = threadIdx.x;
    const int wid = tid >> 5;
    const int wm0 = (wid & 3) * 32;
    const int wn0 = (wid >> 2) * 64;

    wmma::fragment<wmma::accumulator, 16, 16, 16, float> acc[2][4];
#pragma unroll
    for (int i = 0; i < 2; i++)
#pragma unroll
        for (int j = 0; j < 4; j++) wmma::fill_fragment(acc[i][j], 0.0f);

    const int a_row = tid >> 1;
    const int aq = (tid & 1) * 16;
    const __half* arp = rowA(a_row) + aq;
    const int b_row = tid >> 3;
    const int bq = (tid & 7) * 16;
    const __half* brp = Bp + (size_t)b_row * ldb + bq;

    uint4 av0 = *(const uint4*)arp;
    uint4 av1 = *(const uint4*)(arp + 8);
    uint4 bv0 = *(const uint4*)brp;
    uint4 bv1 = *(const uint4*)(brp + 8);

    const int nIter = K / 32;
    for (int it = 0; it < nIter; ++it) {
        const int p = it & 1;
        *(uint4*)&sA[p][a_row][aq]     = av0;
        *(uint4*)&sA[p][a_row][aq + 8] = av1;
        *(uint4*)&sB[p][b_row][bq]     = bv0;
        *(uint4*)&sB[p][b_row][bq + 8] = bv1;
        __syncthreads();
        if (it + 1 < nIter) {
            const int k0 = (it + 1) * 32;
            av0 = *(const uint4*)(arp + k0);
            av1 = *(const uint4*)(arp + k0 + 8);
            bv0 = *(const uint4*)(brp + (size_t)k0 * ldb);
            bv1 = *(const uint4*)(brp + (size_t)k0 * ldb + 8);
        }
#pragma unroll
        for (int ks = 0; ks < 32; ks += 16) {
            wmma::fragment<wmma::matrix_a, 16, 16, 16, __half, wmma::row_major> af[2];
            wmma::fragment<wmma::matrix_b, 16, 16, 16, __half, wmma::row_major> bf[4];
#pragma unroll
            for (int i = 0; i < 2; i++)
                wmma::load_matrix_sync(af[i], &sA[p][wm0 + i * 16][ks], 40);
#pragma unroll
            for (int j = 0; j < 4; j++)
                wmma::load_matrix_sync(bf[j], &sB[p][ks][wn0 + j * 16], 136);
#pragma unroll
            for (int i = 0; i < 2; i++)
#pragma unroll
                for (int j = 0; j < 4; j++)
                    wmma::mma_sync(acc[i][j], af[i], bf[j], acc[i][j]);
        }
        __syncthreads();
    }

#pragma unroll
    for (int i = 0; i < 2; i++)
#pragma unroll
        for (int j = 0; j < 4; j++)
            wmma::store_matrix_sync(&sE[wm0 + i * 16][wn0 + j * 16], acc[i][j], 136,
                                    wmma::mem_row_major);
    __syncthreads();
#pragma unroll
    for (int e = 0; e < 64; e++) {
        const int idx = tid + e * 256;
        const int m = idx >> 7;
        const int n = idx & 127;
        epi(m, n, sE[m][n]);
    }
}

// ---------------- recurrence phase GEMM with cp.async pipeline ----------------
// A: [128 x 1024] fp16 global, B: [1024 x NC] fp16 resident smem. 4-stage pipeline.
// Caller must have issued exactly ONE cp.async group (epilogue operands) before calling.
#define STG_H (128 * 72)          // halves per stage
template<int NC, int MFRAG, typename EpiF>
__device__ __forceinline__ void rec_phase(const __half* __restrict__ Aglob,
                                          const __half* __restrict__ sW,
                                          __half* __restrict__ sA,
                                          float* __restrict__ sE,
                                          EpiF epi)
{
    const int tid = threadIdx.x;
    const int wid = tid >> 5;
    const int wm0 = (MFRAG == 2) ? (wid & 3) * 32 : wid * 16;
    const int wn0 = (MFRAG == 2) ? (wid >> 2) * 16 : 0;

    wmma::fragment<wmma::accumulator, 16, 16, 16, float> acc[MFRAG];
#pragma unroll
    for (int i = 0; i < MFRAG; i++) wmma::fill_fragment(acc[i], 0.0f);

    const int r  = tid >> 3;          // 0..31
    const int c8 = (tid & 7) * 8;     // halves
    const uint32_t sA_base = (uint32_t)__cvta_generic_to_shared(sA);

    auto issue_stage = [&](int j) {
        const uint32_t stg = sA_base + (uint32_t)(j & 3) * (STG_H * 2);
#pragma unroll
        for (int i = 0; i < 4; i++) {
            const int row = r + 32 * i;
            cpa16(stg + (uint32_t)(row * 72 + c8) * 2,
                  Aglob + (size_t)row * HH + j * 64 + c8);
        }
    };

    // prologue: stages 0..2
    issue_stage(0); cpa_commit();
    issue_stage(1); cpa_commit();
    issue_stage(2); cpa_commit();

    for (int it = 0; it < 16; ++it) {
        cpa_wait<2>();
        __syncthreads();
        if (it + 3 < 16) issue_stage(it + 3);
        cpa_commit();                         // commit every iter (possibly empty)
        const __half* Ab = sA + (it & 3) * STG_H;
#pragma unroll
        for (int ks = 0; ks < 64; ks += 16) {
            wmma::fragment<wmma::matrix_a, 16, 16, 16, __half, wmma::row_major> af[MFRAG];
            wmma::fragment<wmma::matrix_b, 16, 16, 16, __half, wmma::row_major> bf;
#pragma unroll
            for (int i = 0; i < MFRAG; i++)
                wmma::load_matrix_sync(af[i], Ab + (wm0 + 16 * i) * 72 + ks, 72);
            wmma::load_matrix_sync(bf, sW + (it * 64 + ks) * NC + wn0, NC);
#pragma unroll
            for (int i = 0; i < MFRAG; i++)
                wmma::mma_sync(acc[i], af[i], bf, acc[i]);
        }
    }
    cpa_wait<0>();
    __syncthreads();
#pragma unroll
    for (int i = 0; i < MFRAG; i++)
        wmma::store_matrix_sync(sE + (wm0 + 16 * i) * (NC + 4) + wn0, acc[i], NC + 4,
                                wmma::mem_row_major);
    __syncthreads();
#pragma unroll
    for (int e = 0; e < (128 * NC) / 256; e++) {
        const int idx = tid + e * 256;
        const int m = idx / NC;
        const int n = idx % NC;
        epi(m, n, sE[m * (NC + 4) + n]);
    }
    __syncthreads();
}

// ---------------- kernels ----------------

__global__ void zero_h_kernel()
{
    int i = blockIdx.x * blockDim.x + threadIdx.x;
    ((float*)g_h)[i] = 0.0f;
    ((__half*)g_hh)[i] = __float2half(0.0f);
}

struct alignas(8) H4 { __half2 a, b; };
__device__ __forceinline__ H4 f2h4(float4 vv)
{
    H4 o;
    o.a = __floats2half2_rn(vv.x, vv.y);
    o.b = __floats2half2_rn(vv.z, vv.w);
    return o;
}

__global__ void f2h_x_kernel(const float4* __restrict__ src, int dir)
{
    int i = blockIdx.x * blockDim.x + threadIdx.x;
    ((H4*)&g_xh[dir][0])[i] = f2h4(src[i]);
}
__global__ void f2h_w_kernel(const float4* __restrict__ src, int slot)
{
    int i = blockIdx.x * blockDim.x + threadIdx.x;
    ((H4*)&g_wh[slot / 3][slot % 3][0])[i] = f2h4(src[i]);
}
__global__ void f2h_wo_kernel(const float4* __restrict__ src)
{
    int i = blockIdx.x * blockDim.x + threadIdx.x;
    ((H4*)&g_woh[0])[i] = f2h4(src[i]);
}

struct ProjArgs { const float* bias[2][3]; };

// grid (24, 512, 2): 128x128 tiles over [65536 x 3072]
__global__ void __launch_bounds__(256) proj_kernel(ProjArgs a)
{
    const int d  = blockIdx.z;
    const int m0 = blockIdx.y * 128;
    const int n0 = blockIdx.x * 128;
    const int g  = n0 >> 10;
    const int nb = n0 & 1023;
    const __half* X  = g_xh[d];
    const __half* Bp = g_wh[d][g] + nb;
    const float*  bs = a.bias[d][g];

    auto rowA = [&](int m) -> const __half* {
        const int rr = m0 + m;
        const int t = rr >> 7;
        const int b = rr & 127;
        return X + ((size_t)b * BT + t) * II;
    };
    auto epi = [&](int m, int n, float vv) {
        const int rr = m0 + m;
        const int c = nb + n;
        g_xp[d][g][rr][c] = __float2half(vv + bs[c]);
    };
    gemm128(II, rowA, Bp, HH, epi);
}

struct RecArgs { const float* U[2][2]; const float* Uh[2]; };

// Dynamic smem layout for recur_kernel:
//   [0      , 65536 )  sW1: 1024 x 32 fp16
//   [65536  , 98304 )  sW2: 1024 x 16 fp16
//   [98304  , 172032)  sA : 4 stages x 128 x 72 fp16   (sE fp32 staging aliases here)
//   [172032 , 180224)  sX : xg/xh tile
//   [180224 , 188416)  sY : hh tile (phase1) / u tile fp32 (phase2)
//   [188416 , 196608)  sZ : h tile fp32 (phase2)
#define REC_SMEM 196608
__global__ void __launch_bounds__(256) recur_kernel(RecArgs a)
{
    extern __shared__ __align__(16) char rsm[];
    __half* sW1 = (__half*)rsm;
    __half* sW2 = (__half*)(rsm + 65536);
    __half* sA  = (__half*)(rsm + 98304);
    float*  sE  = (float*)(rsm + 98304);
    __half* sXh = (__half*)(rsm + 172032);
    __half* sYh = (__half*)(rsm + 180224);
    float*  sU  = (float*)(rsm + 180224);
    float*  sHf = (float*)(rsm + 188416);

    const uint32_t sX_a = (uint32_t)__cvta_generic_to_shared(sXh);
    const uint32_t sY_a = (uint32_t)__cvta_generic_to_shared(sYh);
    const uint32_t sZ_a = (uint32_t)__cvta_generic_to_shared(sHf);

    const int tid = threadIdx.x;
    const int s = blockIdx.x & 63;
    const int d = blockIdx.x >> 6;
    const int g1 = s >> 5;                             // phase1 gate (0=r,1=u)
    const int col0 = (s & 31) * 32;                    // phase1 col base
    const int col2 = s * 16;                           // phase2 col base

    // Load weight slices into smem (fp32 -> fp16), once.
    {
        const float* src1 = a.U[d][g1];
#pragma unroll
        for (int i = 0; i < 32; i++) {
            const int idx = tid + i * 256;
            const int k = idx >> 3, q = idx & 7;
            float4 w = *(const float4*)(src1 + (size_t)k * HH + col0 + q * 4);
            *(__half2*)(sW1 + k * 32 + q * 4)     = __floats2half2_rn(w.x, w.y);
            *(__half2*)(sW1 + k * 32 + q * 4 + 2) = __floats2half2_rn(w.z, w.w);
        }
        const float* src2 = a.Uh[d];
#pragma unroll
        for (int i = 0; i < 16; i++) {
            const int idx = tid + i * 256;
            const int k = idx >> 2, q = idx & 3;
            float4 w = *(const float4*)(src2 + (size_t)k * HH + col2 + q * 4);
            *(__half2*)(sW2 + k * 16 + q * 4)     = __floats2half2_rn(w.x, w.y);
            *(__half2*)(sW2 + k * 16 + q * 4 + 2) = __floats2half2_rn(w.z, w.w);
        }
    }
    __syncthreads();

    for (int t = 0; t < BT; ++t) {
        {   // ---- phase 1 ----
            const __half* xg = &g_xp[d][g1][(size_t)t * BB][0];
            // epilogue operand prefetch (group 0): xg tile, hh tile (gate r only)
            {
#pragma unroll
                for (int rep = 0; rep < 2; rep++) {
                    const int idx = tid + rep * 256;
                    const int row = idx >> 2, q = idx & 3;
                    cpa16(sX_a + (uint32_t)(row * 64 + q * 16),
                          xg + (size_t)row * HH + col0 + q * 8);
                    if (g1 == 0)
                        cpa16(sY_a + (uint32_t)(row * 64 + q * 16),
                              &g_hh[d][row][col0] + q * 8);
                }
                cpa_commit();
            }
            auto epi = [&](int m, int n, float vv) {
                const int c = col0 + n;
                const float sg = sigmoidf_(__half2float(sXh[m * 32 + n]) + vv);
                if (g1 == 0)
                    g_rhh[d][m][c] = __float2half(sg * __half2float(sYh[m * 32 + n]));
                else
                    g_u[d][m][c] = sg;
            };
            rec_phase<32, 2>(&g_hh[d][0][0], sW1, sA, sE, epi);
        }
        grid_barrier();
        {   // ---- phase 2 ----
            const __half* xh = &g_xp[d][2][(size_t)t * BB][0];
            {   // prefetch xh (128x16 fp16), u (128x16 fp32), h (128x16 fp32)
                {
                    const int row = tid >> 1, q = tid & 1;
                    cpa16(sX_a + (uint32_t)(row * 32 + q * 16),
                          xh + (size_t)row * HH + col2 + q * 8);
                }
#pragma unroll
                for (int rep = 0; rep < 2; rep++) {
                    const int idx = tid + rep * 256;
                    const int row = idx >> 2, q = idx & 3;
                    cpa16(sY_a + (uint32_t)(row * 64 + q * 16),
                          &g_u[d][row][col2] + q * 4);
                    cpa16(sZ_a + (uint32_t)(row * 64 + q * 16),
                          &g_h[d][row][col2] + q * 4);
                }
                cpa_commit();
            }
            auto epi = [&](int m, int n, float vv) {
                const int c = col2 + n;
                const float cand = tanhf(__half2float(sXh[m * 16 + n]) + vv);
                const float uu = sU[m * 16 + n];
                const float hp = sHf[m * 16 + n];
                const float hn = uu * hp + (1.0f - uu) * cand;
                g_h[d][m][c] = hn;
                const __half hhv = __float2half(hn);
                g_hh[d][m][c] = hhv;
                g_hcat[(size_t)t * BB + m][d * HH + c] = hhv;
            };
            rec_phase<16, 1>(&g_rhh[d][0][0], sW2, sA, sE, epi);
        }
        grid_barrier();
    }
}

// grid (1, 512)
__global__ void __launch_bounds__(256) out_kernel(const float* __restrict__ bo,
                                                  float* __restrict__ out)
{
    const int m0 = blockIdx.y * 128;
    const __half* Bp = g_woh;

    auto rowA = [&](int m) -> const __half* { return &g_hcat[m0 + m][0]; };
    auto epi = [&](int m, int n, float vv) {
        out[(size_t)(m0 + m) * TGTD + n] = sigmoidf_(vv + bo[n]);
    };
    gemm128(2 * HH, rowA, Bp, TGTD, epi);
}

// ---------------- launch ----------------
extern "C" void kernel_launch(void* const* d_in, const int* in_sizes, int n_in,
                              void* d_out, int out_size)
{
    (void)in_sizes; (void)n_in; (void)out_size;
    const float* fwd = (const float*)d_in[0];
    const float* bwd = (const float*)d_in[1];
    const float* Wr  = (const float*)d_in[2];
    const float* Ur  = (const float*)d_in[3];
    const float* br  = (const float*)d_in[4];
    const float* Wu  = (const float*)d_in[5];
    const float* Uu  = (const float*)d_in[6];
    const float* bu  = (const float*)d_in[7];
    const float* Wh  = (const float*)d_in[8];
    const float* Uh  = (const float*)d_in[9];
    const float* bh  = (const float*)d_in[10];
    const float* Wr1 = (const float*)d_in[11];
    const float* Ur1 = (const float*)d_in[12];
    const float* br1 = (const float*)d_in[13];
    const float* Wu1 = (const float*)d_in[14];
    const float* Uu1 = (const float*)d_in[15];
    const float* bu1 = (const float*)d_in[16];
    const float* Wh1 = (const float*)d_in[17];
    const float* Uh1 = (const float*)d_in[18];
    const float* bh1 = (const float*)d_in[19];
    const float* Wo  = (const float*)d_in[20];
    const float* bo  = (const float*)d_in[21];
    float* out = (float*)d_out;

    static bool attr_done = false;
    if (!attr_done) {
        cudaFuncSetAttribute(recur_kernel, cudaFuncAttributeMaxDynamicSharedMemorySize,
                             REC_SMEM);
        cudaFuncSetAttribute(proj_kernel, cudaFuncAttributeMaxDynamicSharedMemorySize,
                             GEMM128_SMEM);
        cudaFuncSetAttribute(out_kernel, cudaFuncAttributeMaxDynamicSharedMemorySize,
                             GEMM128_SMEM);
        attr_done = true;
    }

    zero_h_kernel<<<(2 * BB * HH) / 1024, 1024>>>();

    {
        const int nx4 = (BB * BT * II) / 4;
        f2h_x_kernel<<<nx4 / 256, 256>>>((const float4*)fwd, 0);
        f2h_x_kernel<<<nx4 / 256, 256>>>((const float4*)bwd, 1);
        const int nw4 = (II * HH) / 4;
        const float* Ws[6] = {Wr, Wu, Wh, Wr1, Wu1, Wh1};
        for (int i = 0; i < 6; i++)
            f2h_w_kernel<<<nw4 / 256, 256>>>((const float4*)Ws[i], i);
        const int no4 = (2 * HH * TGTD) / 4;
        f2h_wo_kernel<<<no4 / 256, 256>>>((const float4*)Wo);
    }

    ProjArgs pa;
    pa.bias[0][0] = br;  pa.bias[0][1] = bu;  pa.bias[0][2] = bh;
    pa.bias[1][0] = br1; pa.bias[1][1] = bu1; pa.bias[1][2] = bh1;
    proj_kernel<<<dim3(3 * HH / 128, MROWS / 128, 2), 256, GEMM128_SMEM>>>(pa);

    RecArgs ra;
    ra.U[0][0] = Ur;  ra.U[0][1] = Uu;
    ra.U[1][0] = Ur1; ra.U[1][1] = Uu1;
    ra.Uh[0] = Uh; ra.Uh[1] = Uh1;
    recur_kernel<<<NBLK, 256, REC_SMEM>>>(ra);

    out_kernel<<<dim3(1, MROWS / 128, 1), 256, GEMM128_SMEM>>>(bo, out);
}